// round 1
// baseline (speedup 1.0000x reference)
#include <cuda_runtime.h>
#include <math.h>

#define BATCH 8
#define CIN   128
#define HID   256
#define DIM   256
#define NSLOT 64
#define LTOK  4096

// ---------------- scratch (device globals; no runtime allocs) ----------------
__device__ float g_wt[3456*256];                  // transposed conv weights [i][c_out]
__device__ float g_k[BATCH*LTOK*DIM];
__device__ float g_v[BATCH*LTOK*DIM];
__device__ float g_templates[BATCH*NSLOT*DIM];
__device__ float g_tbuf[BATCH*NSLOT*DIM];         // LN output (reused for both LNs)
__device__ float g_q[BATCH*NSLOT*DIM];
__device__ float g_attn[BATCH*LTOK*NSLOT];        // softmaxed (pre-renorm) attention
__device__ float g_colsum_part[BATCH*64*NSLOT];
__device__ float g_colsum[BATCH*NSLOT];
__device__ float g_accpart[8*BATCH*NSLOT*DIM];    // split-K partials of attn^T @ v
__device__ float g_hidden[BATCH*NSLOT*512];

#define FMA4(ACC, W, P) do { (ACC).x = fmaf((W).x,(P),(ACC).x); (ACC).y = fmaf((W).y,(P),(ACC).y); \
                             (ACC).z = fmaf((W).z,(P),(ACC).z); (ACC).w = fmaf((W).w,(P),(ACC).w); } while(0)

__device__ __forceinline__ float gelu_exact(float v) {
    return 0.5f * v * (1.0f + erff(v * 0.70710678118654752f));
}

// ---------------- prep kernels ----------------
__global__ void wt_transpose_kernel(const float* __restrict__ cw) {
    // g_wt[i][o] = conv_w[o][i];  conv_w is (256, 3456) row-major
    g_wt[blockIdx.x * 256 + threadIdx.x] = cw[threadIdx.x * 3456 + blockIdx.x];
}

__global__ void templates_init_kernel(const float* __restrict__ tinit) {
    int b = blockIdx.x, t = threadIdx.x;
    for (int n = 0; n < NSLOT; n++)
        g_templates[(b*NSLOT + n)*DIM + t] = tinit[n*DIM + t];
}

// ---------------- conv3d + ReLU + LN(in) + K/V projection (fused) ----------------
// grid: 8*16*16 blocks; block 256 threads; one block = 16 tokens (full w-row) x 256 c_out
#define CONV_SMEM_FLOATS (38016 + 16*256)
__global__ __launch_bounds__(256) void conv_ln_kv_kernel(
    const float* __restrict__ x, const float* __restrict__ convb,
    const float* __restrict__ lng, const float* __restrict__ lnb,
    const float* __restrict__ Wk, const float* __restrict__ Wv)
{
    extern __shared__ float sm[];
    float* patch = sm;            // [c_in*9][33]  (c,kd,kh rows of 33 w values)
    float* toks  = sm + 38016;    // [16][256]

    int bid = blockIdx.x;
    int b  = bid >> 8;
    int xd = (bid >> 4) & 15;
    int xh = bid & 15;
    int t = threadIdx.x;
    int warp = t >> 5, lane = t & 31;

    // ---- load input patch: 128 c_in x 3 kd x 3 kh rows of 33 floats ----
    const float* xb = x + (size_t)b * (CIN*33*33*33);
    for (int r = warp; r < 1152; r += 8) {
        int c = r / 9; int rem = r - c*9; int kd = rem / 3; int kh = rem - kd*3;
        const float* src = xb + ((size_t)(c*33 + (2*xd+kd))*33 + (2*xh+kh))*33;
        patch[r*33 + lane] = src[lane];
        if (lane == 0) patch[r*33 + 32] = src[32];
    }
    __syncthreads();

    // ---- implicit GEMM: thread = (c4 = t&63 -> 4 c_out, tq = t>>6 -> 4 tokens) ----
    int c4 = t & 63;
    int tq = t >> 6;
    float4 acc0, acc1, acc2, acc3;
    float4 bias = *(const float4*)(convb + c4*4);
    acc0 = bias; acc1 = bias; acc2 = bias; acc3 = bias;

    const float4* wt = ((const float4*)g_wt) + c4;   // + i*64 per tap
    const int wb = 8*tq;                              // patch col base: xw = 4tq+tt -> 2*xw = 8tq+2tt

    for (int c = 0; c < CIN; c++) {
        const float* prow = patch + c*9*33;
        const float4* wrow = wt + (c*27)*64;
        #pragma unroll
        for (int kd = 0; kd < 3; kd++) {
            #pragma unroll
            for (int kh = 0; kh < 3; kh++) {
                const float* pr = prow + (kd*3 + kh)*33 + wb;
                const float4* wr = wrow + (kd*9 + kh*3)*64;
                #pragma unroll
                for (int kw = 0; kw < 3; kw++) {
                    float4 w4 = wr[kw*64];
                    float p0 = pr[kw];
                    float p1 = pr[kw+2];
                    float p2 = pr[kw+4];
                    float p3 = pr[kw+6];
                    FMA4(acc0, w4, p0);
                    FMA4(acc1, w4, p1);
                    FMA4(acc2, w4, p2);
                    FMA4(acc3, w4, p3);
                }
            }
        }
    }

    // ReLU + stage tokens in smem
    {
        float4 a;
        a = acc0; a.x=fmaxf(a.x,0.f); a.y=fmaxf(a.y,0.f); a.z=fmaxf(a.z,0.f); a.w=fmaxf(a.w,0.f);
        *(float4*)(toks + (4*tq+0)*256 + c4*4) = a;
        a = acc1; a.x=fmaxf(a.x,0.f); a.y=fmaxf(a.y,0.f); a.z=fmaxf(a.z,0.f); a.w=fmaxf(a.w,0.f);
        *(float4*)(toks + (4*tq+1)*256 + c4*4) = a;
        a = acc2; a.x=fmaxf(a.x,0.f); a.y=fmaxf(a.y,0.f); a.z=fmaxf(a.z,0.f); a.w=fmaxf(a.w,0.f);
        *(float4*)(toks + (4*tq+2)*256 + c4*4) = a;
        a = acc3; a.x=fmaxf(a.x,0.f); a.y=fmaxf(a.y,0.f); a.z=fmaxf(a.z,0.f); a.w=fmaxf(a.w,0.f);
        *(float4*)(toks + (4*tq+3)*256 + c4*4) = a;
    }
    __syncthreads();

    // ---- LayerNorm over 256 channels per token (16 threads/row, 16 chans each) ----
    {
        int r = t >> 4, part = t & 15;
        float* row = toks + r*256 + part*16;
        float s = 0.f, sq = 0.f;
        #pragma unroll
        for (int i = 0; i < 16; i += 4) {
            float4 v = *(float4*)(row + i);
            s += v.x+v.y+v.z+v.w;
            sq += v.x*v.x + v.y*v.y + v.z*v.z + v.w*v.w;
        }
        #pragma unroll
        for (int m = 1; m < 16; m <<= 1) {
            s  += __shfl_xor_sync(0xffffffffu, s, m);
            sq += __shfl_xor_sync(0xffffffffu, sq, m);
        }
        float mu = s * (1.0f/256.0f);
        float var = sq * (1.0f/256.0f) - mu*mu;
        float rs = rsqrtf(var + 1e-5f);
        #pragma unroll
        for (int i = 0; i < 16; i++) {
            int ch = part*16 + i;
            row[i] = (row[i] - mu) * rs * lng[ch] + lnb[ch];
        }
    }
    __syncthreads();

    // ---- K/V projections: 16 tokens x 256 dims each ----
    {
        float4 ak0={0,0,0,0},ak1={0,0,0,0},ak2={0,0,0,0},ak3={0,0,0,0};
        float4 av0={0,0,0,0},av1={0,0,0,0},av2={0,0,0,0},av3={0,0,0,0};
        const float4* wk4 = ((const float4*)Wk) + c4;
        const float4* wv4 = ((const float4*)Wv) + c4;
        const float* t0 = toks + (4*tq+0)*256;
        const float* t1 = toks + (4*tq+1)*256;
        const float* t2 = toks + (4*tq+2)*256;
        const float* t3 = toks + (4*tq+3)*256;
        #pragma unroll 4
        for (int j = 0; j < 256; j++) {
            float4 kw = wk4[j*64];
            float4 vw = wv4[j*64];
            float p0 = t0[j], p1 = t1[j], p2 = t2[j], p3 = t3[j];
            FMA4(ak0, kw, p0); FMA4(ak1, kw, p1); FMA4(ak2, kw, p2); FMA4(ak3, kw, p3);
            FMA4(av0, vw, p0); FMA4(av1, vw, p1); FMA4(av2, vw, p2); FMA4(av3, vw, p3);
        }
        int lbase = ((xd*16 + xh)*16) + 4*tq;
        size_t o0 = ((size_t)b*LTOK + lbase)*DIM + c4*4;
        *(float4*)(g_k + o0)         = ak0; *(float4*)(g_v + o0)         = av0;
        *(float4*)(g_k + o0 + DIM)   = ak1; *(float4*)(g_v + o0 + DIM)   = av1;
        *(float4*)(g_k + o0 + 2*DIM) = ak2; *(float4*)(g_v + o0 + 2*DIM) = av2;
        *(float4*)(g_k + o0 + 3*DIM) = ak3; *(float4*)(g_v + o0 + 3*DIM) = av3;
    }
}

// ---------------- small LayerNorm on templates (8 x 64 x 256), dst = g_tbuf ----------------
__global__ __launch_bounds__(256) void ln_templates_kernel(const float* __restrict__ g,
                                                           const float* __restrict__ bb) {
    int b = blockIdx.x, t = threadIdx.x;
    int r = t >> 2, part = t & 3;
    const float* row = g_templates + ((size_t)(b*NSLOT) + r)*DIM + part*64;
    float s = 0.f, sq = 0.f;
    #pragma unroll
    for (int i = 0; i < 64; i += 4) {
        float4 v = *(const float4*)(row + i);
        s += v.x+v.y+v.z+v.w;
        sq += v.x*v.x + v.y*v.y + v.z*v.z + v.w*v.w;
    }
    #pragma unroll
    for (int m = 1; m < 4; m <<= 1) {
        s  += __shfl_xor_sync(0xffffffffu, s, m);
        sq += __shfl_xor_sync(0xffffffffu, sq, m);
    }
    float mu = s * (1.0f/256.0f);
    float var = sq * (1.0f/256.0f) - mu*mu;
    float rs = rsqrtf(var + 1e-5f);
    float* drow = g_tbuf + ((size_t)(b*NSLOT) + r)*DIM + part*64;
    #pragma unroll
    for (int i = 0; i < 64; i += 4) {
        float4 v = *(const float4*)(row + i);
        float4 gg = *(const float4*)(g + part*64 + i);
        float4 bv = *(const float4*)(bb + part*64 + i);
        float4 o;
        o.x = (v.x - mu)*rs*gg.x + bv.x;
        o.y = (v.y - mu)*rs*gg.y + bv.y;
        o.z = (v.z - mu)*rs*gg.z + bv.z;
        o.w = (v.w - mu)*rs*gg.w + bv.w;
        *(float4*)(drow + i) = o;
    }
}

// ---------------- shared 64x64 tile GEMM core ----------------
// A: M=64 rows x K, row-major (transpose-on-load). B: K x (ldb), direct rows, pre-offset to column tile.
__device__ __forceinline__ void gemm_core_At(const float* __restrict__ A, int lda,
                                             const float* __restrict__ B, int ldb,
                                             int K, float* As, float* Bs,
                                             float4 acc[4]) {
    int t = threadIdx.x;
    int tm = t >> 4, tn = t & 15;
    for (int k0 = 0; k0 < K; k0 += 16) {
        {
            int m = t >> 2, kq = t & 3;
            float4 a4 = *(const float4*)(A + (size_t)m*lda + k0 + kq*4);
            As[(kq*4+0)*64 + m] = a4.x;
            As[(kq*4+1)*64 + m] = a4.y;
            As[(kq*4+2)*64 + m] = a4.z;
            As[(kq*4+3)*64 + m] = a4.w;
        }
        {
            int kk = t >> 4, n4 = (t & 15)*4;
            *(float4*)(Bs + kk*64 + n4) = *(const float4*)(B + (size_t)(k0+kk)*ldb + n4);
        }
        __syncthreads();
        #pragma unroll
        for (int kk = 0; kk < 16; kk++) {
            float4 a = *(float4*)(As + kk*64 + tm*4);
            float4 bb = *(float4*)(Bs + kk*64 + tn*4);
            FMA4(acc[0], bb, a.x);
            FMA4(acc[1], bb, a.y);
            FMA4(acc[2], bb, a.z);
            FMA4(acc[3], bb, a.w);
        }
        __syncthreads();
    }
}

// q = LN_t(templates) @ Wq * scale     grid (4, 8)
__global__ __launch_bounds__(256) void gemm_q_kernel(const float* __restrict__ Wq) {
    int b = blockIdx.y; int nc = blockIdx.x * 64;
    __shared__ float As[1024], Bs[1024];
    float4 acc[4] = {{0,0,0,0},{0,0,0,0},{0,0,0,0},{0,0,0,0}};
    gemm_core_At(g_tbuf + (size_t)b*NSLOT*DIM, DIM, Wq + nc, DIM, DIM, As, Bs, acc);
    int tm = threadIdx.x >> 4, tn = threadIdx.x & 15;
    float* C = g_q + ((size_t)(b*NSLOT) + tm*4)*DIM + nc + tn*4;
    const float scale = 0.0625f;  // 256^-0.5
    #pragma unroll
    for (int i = 0; i < 4; i++) {
        float4 r = acc[i];
        r.x *= scale; r.y *= scale; r.z *= scale; r.w *= scale;
        *(float4*)(C + (size_t)i*DIM) = r;
    }
}

// hidden = GELU(LN_m(templates) @ W1 + b1)   grid (8, 8)
__global__ __launch_bounds__(256) void gemm_h_kernel(const float* __restrict__ W1,
                                                     const float* __restrict__ b1) {
    int b = blockIdx.y; int nc = blockIdx.x * 64;
    __shared__ float As[1024], Bs[1024];
    float4 acc[4] = {{0,0,0,0},{0,0,0,0},{0,0,0,0},{0,0,0,0}};
    gemm_core_At(g_tbuf + (size_t)b*NSLOT*DIM, DIM, W1 + nc, 512, DIM, As, Bs, acc);
    int tm = threadIdx.x >> 4, tn = threadIdx.x & 15;
    float4 bv = *(const float4*)(b1 + nc + tn*4);
    float* C = g_hidden + ((size_t)(b*NSLOT) + tm*4)*512 + nc + tn*4;
    #pragma unroll
    for (int i = 0; i < 4; i++) {
        float4 r = acc[i];
        r.x = gelu_exact(r.x + bv.x);
        r.y = gelu_exact(r.y + bv.y);
        r.z = gelu_exact(r.z + bv.z);
        r.w = gelu_exact(r.w + bv.w);
        *(float4*)(C + (size_t)i*512) = r;
    }
}

// templates += hidden @ W2 + b2          grid (4, 8)
__global__ __launch_bounds__(256) void gemm_o_kernel(const float* __restrict__ W2,
                                                     const float* __restrict__ b2) {
    int b = blockIdx.y; int nc = blockIdx.x * 64;
    __shared__ float As[1024], Bs[1024];
    float4 acc[4] = {{0,0,0,0},{0,0,0,0},{0,0,0,0},{0,0,0,0}};
    gemm_core_At(g_hidden + (size_t)b*NSLOT*512, 512, W2 + nc, DIM, 512, As, Bs, acc);
    int tm = threadIdx.x >> 4, tn = threadIdx.x & 15;
    float4 bv = *(const float4*)(b2 + nc + tn*4);
    float* C = g_templates + ((size_t)(b*NSLOT) + tm*4)*DIM + nc + tn*4;
    #pragma unroll
    for (int i = 0; i < 4; i++) {
        float4 cur = *(float4*)(C + (size_t)i*DIM);
        cur.x += acc[i].x + bv.x;
        cur.y += acc[i].y + bv.y;
        cur.z += acc[i].z + bv.z;
        cur.w += acc[i].w + bv.w;
        *(float4*)(C + (size_t)i*DIM) = cur;
    }
}

// attn logits (64 l x 64 n, K=256) + softmax over n + column-sum partials.  grid (64, 8)
__global__ __launch_bounds__(256) void attn_softmax_kernel() {
    int lb = blockIdx.x, b = blockIdx.y;
    const float* A = g_k + ((size_t)b*LTOK + lb*64)*DIM;   // rows = l
    const float* Q = g_q + (size_t)b*NSLOT*DIM;            // rows = n
    __shared__ float As[1024], Bs[1024];
    float4 acc[4] = {{0,0,0,0},{0,0,0,0},{0,0,0,0},{0,0,0,0}};
    int t = threadIdx.x;
    int tm = t >> 4, tn = t & 15;
    for (int k0 = 0; k0 < 256; k0 += 16) {
        int m = t >> 2, kq = t & 3;
        float4 a4 = *(const float4*)(A + (size_t)m*DIM + k0 + kq*4);
        As[(kq*4+0)*64 + m] = a4.x;
        As[(kq*4+1)*64 + m] = a4.y;
        As[(kq*4+2)*64 + m] = a4.z;
        As[(kq*4+3)*64 + m] = a4.w;
        float4 b4 = *(const float4*)(Q + (size_t)m*DIM + k0 + kq*4);
        Bs[(kq*4+0)*64 + m] = b4.x;
        Bs[(kq*4+1)*64 + m] = b4.y;
        Bs[(kq*4+2)*64 + m] = b4.z;
        Bs[(kq*4+3)*64 + m] = b4.w;
        __syncthreads();
        #pragma unroll
        for (int kk = 0; kk < 16; kk++) {
            float4 a = *(float4*)(As + kk*64 + tm*4);
            float4 bb = *(float4*)(Bs + kk*64 + tn*4);
            FMA4(acc[0], bb, a.x);
            FMA4(acc[1], bb, a.y);
            FMA4(acc[2], bb, a.z);
            FMA4(acc[3], bb, a.w);
        }
        __syncthreads();
    }
    // softmax over n (64 values spread across the 16 tn lanes) for each of 4 rows
    float4 csum = {0,0,0,0};
    #pragma unroll
    for (int i = 0; i < 4; i++) {
        float4 r = acc[i];
        float mx = fmaxf(fmaxf(r.x, r.y), fmaxf(r.z, r.w));
        #pragma unroll
        for (int m = 1; m < 16; m <<= 1) mx = fmaxf(mx, __shfl_xor_sync(0xffffffffu, mx, m));
        float e0 = expf(r.x - mx), e1 = expf(r.y - mx), e2 = expf(r.z - mx), e3 = expf(r.w - mx);
        float s = e0 + e1 + e2 + e3;
        #pragma unroll
        for (int m = 1; m < 16; m <<= 1) s += __shfl_xor_sync(0xffffffffu, s, m);
        float inv = 1.0f / s;
        float4 a;
        a.x = e0*inv + 1e-8f; a.y = e1*inv + 1e-8f; a.z = e2*inv + 1e-8f; a.w = e3*inv + 1e-8f;
        *(float4*)(g_attn + ((size_t)b*LTOK + lb*64 + tm*4 + i)*NSLOT + tn*4) = a;
        csum.x += a.x; csum.y += a.y; csum.z += a.z; csum.w += a.w;
    }
    // column-sum partials: reduce over tm via smem (reuse As)
    *(float4*)(As + tm*64 + tn*4) = csum;
    __syncthreads();
    if (t < 64) {
        float s = 0.f;
        #pragma unroll
        for (int r = 0; r < 16; r++) s += As[r*64 + t];
        g_colsum_part[((size_t)b*64 + lb)*NSLOT + t] = s;
    }
}

__global__ void colsum_reduce_kernel() {  // grid 8, block 64
    int b = blockIdx.x, n = threadIdx.x;
    float s = 0.f;
    for (int lb = 0; lb < 64; lb++) s += g_colsum_part[((size_t)b*64 + lb)*NSLOT + n];
    g_colsum[b*NSLOT + n] = s;
}

// acc_part[p][b] = attn_chunk^T @ v_chunk  (M=64 slots, N=64 dim tile, K=512 l)  grid (4, 8, 8)
__global__ __launch_bounds__(256) void gemm_c_kernel() {
    int dt = blockIdx.x, p = blockIdx.y, b = blockIdx.z;
    const float* A = g_attn + ((size_t)b*LTOK + p*512)*NSLOT;      // [l][n] direct
    const float* B = g_v    + ((size_t)b*LTOK + p*512)*DIM + dt*64;
    __shared__ float As[1024], Bs[1024];
    float4 acc[4] = {{0,0,0,0},{0,0,0,0},{0,0,0,0},{0,0,0,0}};
    int t = threadIdx.x;
    int tm = t >> 4, tn = t & 15;
    int kk = t >> 4, n4 = (t & 15)*4;
    for (int k0 = 0; k0 < 512; k0 += 16) {
        *(float4*)(As + kk*64 + n4) = *(const float4*)(A + (size_t)(k0+kk)*NSLOT + n4);
        *(float4*)(Bs + kk*64 + n4) = *(const float4*)(B + (size_t)(k0+kk)*DIM + n4);
        __syncthreads();
        #pragma unroll
        for (int k = 0; k < 16; k++) {
            float4 a = *(float4*)(As + k*64 + tm*4);
            float4 bb = *(float4*)(Bs + k*64 + tn*4);
            FMA4(acc[0], bb, a.x);
            FMA4(acc[1], bb, a.y);
            FMA4(acc[2], bb, a.z);
            FMA4(acc[3], bb, a.w);
        }
        __syncthreads();
    }
    float* C = g_accpart + ((size_t)((p*BATCH + b)*NSLOT) + tm*4)*DIM + dt*64 + tn*4;
    #pragma unroll
    for (int i = 0; i < 4; i++) *(float4*)(C + (size_t)i*DIM) = acc[i];
}

// templates = t_prev + (sum_p acc_part) / colsum     grid 8, block 256
__global__ void finalize_kernel() {
    int b = blockIdx.x, t = threadIdx.x;
    for (int n = 0; n < NSLOT; n++) {
        float s = 0.f;
        #pragma unroll
        for (int p = 0; p < 8; p++)
            s += g_accpart[((size_t)((p*BATCH + b)*NSLOT) + n)*DIM + t];
        size_t idx = ((size_t)(b*NSLOT) + n)*DIM + t;
        g_templates[idx] += s / g_colsum[b*NSLOT + n];
    }
}

// ---------------- outputs ----------------
__global__ void out_templates_kernel(float* __restrict__ out) {  // grid 8, block 256
    int b = blockIdx.x, d = threadIdx.x;
    for (int n = 0; n < NSLOT; n++)
        out[((size_t)(b*DIM) + d)*NSLOT + n] = g_templates[((size_t)(b*NSLOT) + n)*DIM + d];
}

__global__ void out_attn_kernel(float* __restrict__ out) {       // grid (64, 8), block 256
    int n = blockIdx.x, b = blockIdx.y, t = threadIdx.x;
    float inv = 1.0f / g_colsum[b*NSLOT + n];
    size_t base = (size_t)BATCH*DIM*NSLOT + ((size_t)(b*NSLOT + n))*LTOK;
    for (int k = 0; k < 16; k++) {
        int l = k*256 + t;
        out[base + l] = g_attn[((size_t)b*LTOK + l)*NSLOT + n] * inv;
    }
}

// ---------------- launch ----------------
extern "C" void kernel_launch(void* const* d_in, const int* in_sizes, int n_in,
                              void* d_out, int out_size) {
    const float* x       = (const float*)d_in[0];
    const float* tinit   = (const float*)d_in[1];
    const float* conv_w  = (const float*)d_in[2];
    const float* conv_b  = (const float*)d_in[3];
    const float* Wq      = (const float*)d_in[4];
    const float* Wk      = (const float*)d_in[5];
    const float* Wv      = (const float*)d_in[6];
    const float* ln_in_g = (const float*)d_in[7];
    const float* ln_in_b = (const float*)d_in[8];
    const float* ln_t_g  = (const float*)d_in[9];
    const float* ln_t_b  = (const float*)d_in[10];
    const float* ln_m_g  = (const float*)d_in[11];
    const float* ln_m_b  = (const float*)d_in[12];
    const float* W1      = (const float*)d_in[13];
    const float* b1      = (const float*)d_in[14];
    const float* W2      = (const float*)d_in[15];
    const float* b2      = (const float*)d_in[16];
    float* out = (float*)d_out;

    cudaFuncSetAttribute(conv_ln_kv_kernel, cudaFuncAttributeMaxDynamicSharedMemorySize,
                         CONV_SMEM_FLOATS * 4);

    wt_transpose_kernel<<<3456, 256>>>(conv_w);
    templates_init_kernel<<<8, 256>>>(tinit);
    conv_ln_kv_kernel<<<2048, 256, CONV_SMEM_FLOATS * 4>>>(x, conv_b, ln_in_g, ln_in_b, Wk, Wv);

    for (int it = 0; it < 6; it++) {
        ln_templates_kernel<<<8, 256>>>(ln_t_g, ln_t_b);
        gemm_q_kernel<<<dim3(4, 8), 256>>>(Wq);
        attn_softmax_kernel<<<dim3(64, 8), 256>>>();
        colsum_reduce_kernel<<<8, 64>>>();
        gemm_c_kernel<<<dim3(4, 8, 8), 256>>>();
        finalize_kernel<<<8, 256>>>();
        ln_templates_kernel<<<8, 256>>>(ln_m_g, ln_m_b);
        gemm_h_kernel<<<dim3(8, 8), 256>>>(W1, b1);
        gemm_o_kernel<<<dim3(4, 8), 256>>>(W2, b2);
    }

    out_templates_kernel<<<8, 256>>>(out);
    out_attn_kernel<<<dim3(64, 8), 256>>>(out);
}

// round 4
// speedup vs baseline: 1.0264x; 1.0264x over previous
#include <cuda_runtime.h>
#include <math.h>

#define BATCH 8
#define CIN   128
#define DIM   256
#define NSLOT 64
#define LTOK  4096

typedef unsigned long long u64;

__device__ __forceinline__ u64 PK1(float v) {
    u64 r; asm("mov.b64 %0, {%1,%1};" : "=l"(r) : "f"(v)); return r;
}
__device__ __forceinline__ void FMA2(u64& d, u64 a, u64 b) {
    asm("fma.rn.f32x2 %0, %1, %2, %0;" : "+l"(d) : "l"(a), "l"(b));
}
__device__ __forceinline__ float2 UPK(u64 v) {
    float2 f; asm("mov.b64 {%0,%1}, %2;" : "=f"(f.x), "=f"(f.y) : "l"(v)); return f;
}

// ---------------- scratch ----------------
__device__ float g_wt[3456*256];
__device__ float g_k[BATCH*LTOK*DIM];
__device__ float g_v[BATCH*LTOK*DIM];
__device__ float g_templates[BATCH*NSLOT*DIM];
__device__ float g_tbuf[BATCH*NSLOT*DIM];
__device__ float g_q[BATCH*NSLOT*DIM];
__device__ float g_attn[BATCH*LTOK*NSLOT];
__device__ float g_colsum_part[BATCH*64*NSLOT];
__device__ float g_colsum[BATCH*NSLOT];
__device__ float g_accpart[8*BATCH*NSLOT*DIM];
__device__ float g_hidden[BATCH*NSLOT*512];

__device__ __forceinline__ float gelu_exact(float v) {
    return 0.5f * v * (1.0f + erff(v * 0.70710678118654752f));
}

// ---------------- prep ----------------
__global__ void wt_transpose_kernel(const float* __restrict__ cw) {
    g_wt[blockIdx.x * 256 + threadIdx.x] = cw[threadIdx.x * 3456 + blockIdx.x];
}

__global__ void templates_init_kernel(const float* __restrict__ tinit) {
    int b = blockIdx.x, t = threadIdx.x;
    for (int n = 0; n < NSLOT; n++)
        g_templates[(b*NSLOT + n)*DIM + t] = tinit[n*DIM + t];
}

// ---------------- conv3d + ReLU + LN + K/V projection ----------------
#define CONV_SMEM_FLOATS (38016 + 16*256)
__global__ __launch_bounds__(256) void conv_ln_kv_kernel(
    const float* __restrict__ x, const float* __restrict__ convb,
    const float* __restrict__ lng, const float* __restrict__ lnb,
    const float* __restrict__ Wk, const float* __restrict__ Wv)
{
    extern __shared__ float sm[];
    float* patch = sm;            // [c_in*9][33]
    float* toks  = sm + 38016;    // [16][256]

    int bid = blockIdx.x;
    int b  = bid >> 8;
    int xd = (bid >> 4) & 15;
    int xh = bid & 15;
    int t = threadIdx.x;
    int warp = t >> 5, lane = t & 31;

    const float* xb = x + (size_t)b * (CIN*33*33*33);
    for (int r = warp; r < 1152; r += 8) {
        int c = r / 9; int rem = r - c*9; int kd = rem / 3; int kh = rem - kd*3;
        const float* src = xb + ((size_t)(c*33 + (2*xd+kd))*33 + (2*xh+kh))*33;
        patch[r*33 + lane] = src[lane];
        if (lane == 0) patch[r*33 + 32] = src[32];
    }
    __syncthreads();

    int c4 = t & 63;   // 4 c_out (2 f32x2 pairs)
    int tq = t >> 6;   // 4 tokens
    u64 acc[4][2];
    {
        ulonglong2 b2 = *(const ulonglong2*)(convb + c4*4);
        #pragma unroll
        for (int i = 0; i < 4; i++) { acc[i][0] = b2.x; acc[i][1] = b2.y; }
    }

    const ulonglong2* wt = ((const ulonglong2*)g_wt) + c4;  // row stride 64
    const int wb = 8*tq;

    for (int c = 0; c < CIN; c++) {
        const float* prow = patch + c*297;
        const ulonglong2* wrow = wt + (size_t)(c*27)*64;
        #pragma unroll
        for (int kd = 0; kd < 3; kd++) {
            #pragma unroll
            for (int kh = 0; kh < 3; kh++) {
                const float* pr = prow + (kd*3 + kh)*33 + wb;
                const ulonglong2* wr = wrow + (kd*9 + kh*3)*64;
                #pragma unroll
                for (int kw = 0; kw < 3; kw++) {
                    ulonglong2 w = wr[(size_t)kw*64];
                    u64 q0 = PK1(pr[kw]);
                    u64 q1 = PK1(pr[kw+2]);
                    u64 q2 = PK1(pr[kw+4]);
                    u64 q3 = PK1(pr[kw+6]);
                    FMA2(acc[0][0], w.x, q0); FMA2(acc[0][1], w.y, q0);
                    FMA2(acc[1][0], w.x, q1); FMA2(acc[1][1], w.y, q1);
                    FMA2(acc[2][0], w.x, q2); FMA2(acc[2][1], w.y, q2);
                    FMA2(acc[3][0], w.x, q3); FMA2(acc[3][1], w.y, q3);
                }
            }
        }
    }

    #pragma unroll
    for (int i = 0; i < 4; i++) {
        float2 a = UPK(acc[i][0]), bb2 = UPK(acc[i][1]);
        float4 o;
        o.x = fmaxf(a.x, 0.f);  o.y = fmaxf(a.y, 0.f);
        o.z = fmaxf(bb2.x, 0.f); o.w = fmaxf(bb2.y, 0.f);
        *(float4*)(toks + (4*tq+i)*256 + c4*4) = o;
    }
    __syncthreads();

    // LayerNorm per token (16 threads/row)
    {
        int r = t >> 4, part = t & 15;
        float* row = toks + r*256 + part*16;
        float s = 0.f, sq = 0.f;
        #pragma unroll
        for (int i = 0; i < 16; i += 4) {
            float4 v = *(float4*)(row + i);
            s += v.x+v.y+v.z+v.w;
            sq += v.x*v.x + v.y*v.y + v.z*v.z + v.w*v.w;
        }
        #pragma unroll
        for (int m = 1; m < 16; m <<= 1) {
            s  += __shfl_xor_sync(0xffffffffu, s, m);
            sq += __shfl_xor_sync(0xffffffffu, sq, m);
        }
        float mu = s * (1.0f/256.0f);
        float var = sq * (1.0f/256.0f) - mu*mu;
        float rs = rsqrtf(var + 1e-5f);
        #pragma unroll
        for (int i = 0; i < 16; i++) {
            int ch = part*16 + i;
            row[i] = (row[i] - mu) * rs * lng[ch] + lnb[ch];
        }
    }
    __syncthreads();

    // K/V projections (f32x2)
    {
        u64 ka[4][2] = {}, va[4][2] = {};
        const ulonglong2* wk2 = ((const ulonglong2*)Wk) + c4;
        const ulonglong2* wv2 = ((const ulonglong2*)Wv) + c4;
        const float* t0 = toks + (4*tq+0)*256;
        const float* t1 = toks + (4*tq+1)*256;
        const float* t2 = toks + (4*tq+2)*256;
        const float* t3 = toks + (4*tq+3)*256;
        #pragma unroll 4
        for (int j = 0; j < 256; j++) {
            ulonglong2 kw = wk2[(size_t)j*64];
            ulonglong2 vw = wv2[(size_t)j*64];
            u64 p0 = PK1(t0[j]), p1 = PK1(t1[j]), p2 = PK1(t2[j]), p3 = PK1(t3[j]);
            FMA2(ka[0][0],kw.x,p0); FMA2(ka[0][1],kw.y,p0); FMA2(va[0][0],vw.x,p0); FMA2(va[0][1],vw.y,p0);
            FMA2(ka[1][0],kw.x,p1); FMA2(ka[1][1],kw.y,p1); FMA2(va[1][0],vw.x,p1); FMA2(va[1][1],vw.y,p1);
            FMA2(ka[2][0],kw.x,p2); FMA2(ka[2][1],kw.y,p2); FMA2(va[2][0],vw.x,p2); FMA2(va[2][1],vw.y,p2);
            FMA2(ka[3][0],kw.x,p3); FMA2(ka[3][1],kw.y,p3); FMA2(va[3][0],vw.x,p3); FMA2(va[3][1],vw.y,p3);
        }
        int lbase = ((xd*16 + xh)*16) + 4*tq;
        size_t o0 = ((size_t)b*LTOK + lbase)*DIM + c4*4;
        #pragma unroll
        for (int i = 0; i < 4; i++) {
            *(ulonglong2*)(g_k + o0 + (size_t)i*DIM) = make_ulonglong2(ka[i][0], ka[i][1]);
            *(ulonglong2*)(g_v + o0 + (size_t)i*DIM) = make_ulonglong2(va[i][0], va[i][1]);
        }
    }
}

// ---------------- fused LN_t + q-GEMM ----------------
// grid (4, 8), block 256. smem: Af[256*64] transposed LN'd A + Bs[16*64]
__global__ __launch_bounds__(256) void gemm_q_kernel(
    const float* __restrict__ Wq, const float* __restrict__ lng, const float* __restrict__ lnb)
{
    extern __shared__ float sm[];
    float* Af = sm;            // [k][m] 256x64
    float* Bs = sm + 16384;
    int b = blockIdx.y; int nc = blockIdx.x * 64;
    int t = threadIdx.x;

    // LN staging: 4 threads/row, write transposed
    {
        int r = t >> 2, part = t & 3;
        const float* row = g_templates + ((size_t)(b*NSLOT) + r)*DIM + part*64;
        float s = 0.f, sq = 0.f;
        #pragma unroll
        for (int i = 0; i < 64; i += 4) {
            float4 v = *(const float4*)(row + i);
            s += v.x+v.y+v.z+v.w;
            sq += v.x*v.x + v.y*v.y + v.z*v.z + v.w*v.w;
        }
        s  += __shfl_xor_sync(0xffffffffu, s, 1);  s  += __shfl_xor_sync(0xffffffffu, s, 2);
        sq += __shfl_xor_sync(0xffffffffu, sq, 1); sq += __shfl_xor_sync(0xffffffffu, sq, 2);
        float mu = s * (1.0f/256.0f);
        float rs = rsqrtf(sq * (1.0f/256.0f) - mu*mu + 1e-5f);
        #pragma unroll
        for (int i = 0; i < 64; i += 4) {
            float4 v = *(const float4*)(row + i);
            float4 gg = *(const float4*)(lng + part*64 + i);
            float4 bv = *(const float4*)(lnb + part*64 + i);
            Af[(part*64+i+0)*64 + r] = (v.x - mu)*rs*gg.x + bv.x;
            Af[(part*64+i+1)*64 + r] = (v.y - mu)*rs*gg.y + bv.y;
            Af[(part*64+i+2)*64 + r] = (v.z - mu)*rs*gg.z + bv.z;
            Af[(part*64+i+3)*64 + r] = (v.w - mu)*rs*gg.w + bv.w;
        }
    }
    __syncthreads();

    int tm = t >> 4, tn = t & 15;
    u64 acc[4][2] = {};
    int kk0 = t >> 4, n4 = (t & 15)*4;
    for (int k0 = 0; k0 < 256; k0 += 16) {
        *(float4*)(Bs + kk0*64 + n4) = *(const float4*)(Wq + (size_t)(k0+kk0)*256 + nc + n4);
        __syncthreads();
        #pragma unroll
        for (int kk = 0; kk < 16; kk++) {
            ulonglong2 a2 = *(ulonglong2*)(Af + (k0+kk)*64 + tm*4);
            float4 bb = *(float4*)(Bs + kk*64 + tn*4);
            u64 q0 = PK1(bb.x), q1 = PK1(bb.y), q2 = PK1(bb.z), q3 = PK1(bb.w);
            FMA2(acc[0][0], a2.x, q0); FMA2(acc[0][1], a2.y, q0);
            FMA2(acc[1][0], a2.x, q1); FMA2(acc[1][1], a2.y, q1);
            FMA2(acc[2][0], a2.x, q2); FMA2(acc[2][1], a2.y, q2);
            FMA2(acc[3][0], a2.x, q3); FMA2(acc[3][1], a2.y, q3);
        }
        __syncthreads();
    }
    const float scale = 0.0625f;
    #pragma unroll
    for (int p = 0; p < 2; p++) {
        float2 f0 = UPK(acc[0][p]), f1 = UPK(acc[1][p]), f2 = UPK(acc[2][p]), f3 = UPK(acc[3][p]);
        float4 r0 = {f0.x*scale, f1.x*scale, f2.x*scale, f3.x*scale};
        float4 r1 = {f0.y*scale, f1.y*scale, f2.y*scale, f3.y*scale};
        int m = tm*4 + p*2;
        *(float4*)(g_q + ((size_t)(b*NSLOT) + m  )*DIM + nc + tn*4) = r0;
        *(float4*)(g_q + ((size_t)(b*NSLOT) + m+1)*DIM + nc + tn*4) = r1;
    }
}

// ---------------- hidden = GELU(LN_m(templates) @ W1 + b1), A = g_tbuf ----------------
__global__ __launch_bounds__(256) void gemm_h_kernel(const float* __restrict__ W1,
                                                     const float* __restrict__ b1)
{
    extern __shared__ float sm[];
    float* Af = sm; float* Bs = sm + 16384;
    int b = blockIdx.y; int nc = blockIdx.x * 64;
    int t = threadIdx.x;
    {
        int r = t >> 2, part = t & 3;
        const float* row = g_tbuf + ((size_t)(b*NSLOT) + r)*DIM + part*64;
        #pragma unroll
        for (int i = 0; i < 64; i += 4) {
            float4 v = *(const float4*)(row + i);
            Af[(part*64+i+0)*64 + r] = v.x;
            Af[(part*64+i+1)*64 + r] = v.y;
            Af[(part*64+i+2)*64 + r] = v.z;
            Af[(part*64+i+3)*64 + r] = v.w;
        }
    }
    __syncthreads();
    int tm = t >> 4, tn = t & 15;
    u64 acc[4][2] = {};
    int kk0 = t >> 4, n4 = (t & 15)*4;
    for (int k0 = 0; k0 < 256; k0 += 16) {
        *(float4*)(Bs + kk0*64 + n4) = *(const float4*)(W1 + (size_t)(k0+kk0)*512 + nc + n4);
        __syncthreads();
        #pragma unroll
        for (int kk = 0; kk < 16; kk++) {
            ulonglong2 a2 = *(ulonglong2*)(Af + (k0+kk)*64 + tm*4);
            float4 bb = *(float4*)(Bs + kk*64 + tn*4);
            u64 q0 = PK1(bb.x), q1 = PK1(bb.y), q2 = PK1(bb.z), q3 = PK1(bb.w);
            FMA2(acc[0][0], a2.x, q0); FMA2(acc[0][1], a2.y, q0);
            FMA2(acc[1][0], a2.x, q1); FMA2(acc[1][1], a2.y, q1);
            FMA2(acc[2][0], a2.x, q2); FMA2(acc[2][1], a2.y, q2);
            FMA2(acc[3][0], a2.x, q3); FMA2(acc[3][1], a2.y, q3);
        }
        __syncthreads();
    }
    float4 bv = *(const float4*)(b1 + nc + tn*4);
    #pragma unroll
    for (int p = 0; p < 2; p++) {
        float2 f0 = UPK(acc[0][p]), f1 = UPK(acc[1][p]), f2 = UPK(acc[2][p]), f3 = UPK(acc[3][p]);
        float4 r0 = {gelu_exact(f0.x+bv.x), gelu_exact(f1.x+bv.y), gelu_exact(f2.x+bv.z), gelu_exact(f3.x+bv.w)};
        float4 r1 = {gelu_exact(f0.y+bv.x), gelu_exact(f1.y+bv.y), gelu_exact(f2.y+bv.z), gelu_exact(f3.y+bv.w)};
        int m = tm*4 + p*2;
        *(float4*)(g_hidden + ((size_t)(b*NSLOT) + m  )*512 + nc + tn*4) = r0;
        *(float4*)(g_hidden + ((size_t)(b*NSLOT) + m+1)*512 + nc + tn*4) = r1;
    }
}

// ---------------- templates += hidden @ W2 + b2 ----------------
#define GEMMO_SMEM_FLOATS (32768 + 1024)
__global__ __launch_bounds__(256) void gemm_o_kernel(const float* __restrict__ W2,
                                                     const float* __restrict__ b2)
{
    extern __shared__ float sm[];
    float* Af = sm;            // 512 x 64
    float* Bs = sm + 32768;
    int b = blockIdx.y; int nc = blockIdx.x * 64;
    int t = threadIdx.x;
    {
        int r = t >> 2, part = t & 3;
        const float* row = g_hidden + ((size_t)(b*NSLOT) + r)*512 + part*128;
        #pragma unroll
        for (int i = 0; i < 128; i += 4) {
            float4 v = *(const float4*)(row + i);
            Af[(part*128+i+0)*64 + r] = v.x;
            Af[(part*128+i+1)*64 + r] = v.y;
            Af[(part*128+i+2)*64 + r] = v.z;
            Af[(part*128+i+3)*64 + r] = v.w;
        }
    }
    __syncthreads();
    int tm = t >> 4, tn = t & 15;
    u64 acc[4][2] = {};
    int kk0 = t >> 4, n4 = (t & 15)*4;
    for (int k0 = 0; k0 < 512; k0 += 16) {
        *(float4*)(Bs + kk0*64 + n4) = *(const float4*)(W2 + (size_t)(k0+kk0)*256 + nc + n4);
        __syncthreads();
        #pragma unroll
        for (int kk = 0; kk < 16; kk++) {
            ulonglong2 a2 = *(ulonglong2*)(Af + (k0+kk)*64 + tm*4);
            float4 bb = *(float4*)(Bs + kk*64 + tn*4);
            u64 q0 = PK1(bb.x), q1 = PK1(bb.y), q2 = PK1(bb.z), q3 = PK1(bb.w);
            FMA2(acc[0][0], a2.x, q0); FMA2(acc[0][1], a2.y, q0);
            FMA2(acc[1][0], a2.x, q1); FMA2(acc[1][1], a2.y, q1);
            FMA2(acc[2][0], a2.x, q2); FMA2(acc[2][1], a2.y, q2);
            FMA2(acc[3][0], a2.x, q3); FMA2(acc[3][1], a2.y, q3);
        }
        __syncthreads();
    }
    float4 bv = *(const float4*)(b2 + nc + tn*4);
    #pragma unroll
    for (int p = 0; p < 2; p++) {
        float2 f0 = UPK(acc[0][p]), f1 = UPK(acc[1][p]), f2 = UPK(acc[2][p]), f3 = UPK(acc[3][p]);
        int m = tm*4 + p*2;
        float* C0 = g_templates + ((size_t)(b*NSLOT) + m)*DIM + nc + tn*4;
        float4 c0 = *(float4*)C0;
        c0.x += f0.x + bv.x; c0.y += f1.x + bv.y; c0.z += f2.x + bv.z; c0.w += f3.x + bv.w;
        *(float4*)C0 = c0;
        float* C1 = C0 + DIM;
        float4 c1 = *(float4*)C1;
        c1.x += f0.y + bv.x; c1.y += f1.y + bv.y; c1.z += f2.y + bv.z; c1.w += f3.y + bv.w;
        *(float4*)C1 = c1;
    }
}

// ---------------- attn logits + softmax + colsum partials. grid (64, 8) ----------------
__global__ __launch_bounds__(256) void attn_softmax_kernel() {
    int lb = blockIdx.x, b = blockIdx.y;
    const float* A = g_k + ((size_t)b*LTOK + lb*64)*DIM;
    const float* Q = g_q + (size_t)b*NSLOT*DIM;
    __shared__ float As[1024], Bs[1024];
    u64 acc[4][2] = {};
    int t = threadIdx.x;
    int tm = t >> 4, tn = t & 15;
    for (int k0 = 0; k0 < 256; k0 += 16) {
        int m = t >> 2, kq = t & 3;
        float4 a4 = *(const float4*)(A + (size_t)m*DIM + k0 + kq*4);
        As[(kq*4+0)*64 + m] = a4.x;
        As[(kq*4+1)*64 + m] = a4.y;
        As[(kq*4+2)*64 + m] = a4.z;
        As[(kq*4+3)*64 + m] = a4.w;
        float4 b4 = *(const float4*)(Q + (size_t)m*DIM + k0 + kq*4);
        Bs[(kq*4+0)*64 + m] = b4.x;
        Bs[(kq*4+1)*64 + m] = b4.y;
        Bs[(kq*4+2)*64 + m] = b4.z;
        Bs[(kq*4+3)*64 + m] = b4.w;
        __syncthreads();
        #pragma unroll
        for (int kk = 0; kk < 16; kk++) {
            ulonglong2 a2 = *(ulonglong2*)(As + kk*64 + tm*4);
            float4 bb = *(float4*)(Bs + kk*64 + tn*4);
            u64 q0 = PK1(bb.x), q1 = PK1(bb.y), q2 = PK1(bb.z), q3 = PK1(bb.w);
            FMA2(acc[0][0], a2.x, q0); FMA2(acc[0][1], a2.y, q0);
            FMA2(acc[1][0], a2.x, q1); FMA2(acc[1][1], a2.y, q1);
            FMA2(acc[2][0], a2.x, q2); FMA2(acc[2][1], a2.y, q2);
            FMA2(acc[3][0], a2.x, q3); FMA2(acc[3][1], a2.y, q3);
        }
        __syncthreads();
    }
    // softmax over n per l-row; rows = tm*4 + p*2 + h
    float4 csum = {0,0,0,0};
    #pragma unroll
    for (int p = 0; p < 2; p++) {
        float2 f0 = UPK(acc[0][p]), f1 = UPK(acc[1][p]), f2 = UPK(acc[2][p]), f3 = UPK(acc[3][p]);
        #pragma unroll
        for (int h = 0; h < 2; h++) {
            float v0 = h ? f0.y : f0.x;
            float v1 = h ? f1.y : f1.x;
            float v2 = h ? f2.y : f2.x;
            float v3 = h ? f3.y : f3.x;
            float mx = fmaxf(fmaxf(v0, v1), fmaxf(v2, v3));
            #pragma unroll
            for (int m = 1; m < 16; m <<= 1) mx = fmaxf(mx, __shfl_xor_sync(0xffffffffu, mx, m));
            float e0 = expf(v0 - mx), e1 = expf(v1 - mx), e2 = expf(v2 - mx), e3 = expf(v3 - mx);
            float s = e0 + e1 + e2 + e3;
            #pragma unroll
            for (int m = 1; m < 16; m <<= 1) s += __shfl_xor_sync(0xffffffffu, s, m);
            float inv = 1.0f / s;
            float4 a;
            a.x = e0*inv + 1e-8f; a.y = e1*inv + 1e-8f; a.z = e2*inv + 1e-8f; a.w = e3*inv + 1e-8f;
            int row = tm*4 + p*2 + h;
            *(float4*)(g_attn + ((size_t)b*LTOK + lb*64 + row)*NSLOT + tn*4) = a;
            csum.x += a.x; csum.y += a.y; csum.z += a.z; csum.w += a.w;
        }
    }
    *(float4*)(As + tm*64 + tn*4) = csum;
    __syncthreads();
    if (t < 64) {
        float s = 0.f;
        #pragma unroll
        for (int r = 0; r < 16; r++) s += As[r*64 + t];
        g_colsum_part[((size_t)b*64 + lb)*NSLOT + t] = s;
    }
}

// ---------------- attn^T @ v split-K partials. grid (4, 8, 8) ----------------
__global__ __launch_bounds__(256) void gemm_c_kernel() {
    int dt = blockIdx.x, ps = blockIdx.y, b = blockIdx.z;
    const float* A = g_attn + ((size_t)b*LTOK + ps*512)*NSLOT;   // [l][slot]
    const float* B = g_v    + ((size_t)b*LTOK + ps*512)*DIM + dt*64;
    __shared__ float As[1024], Bs[1024];
    u64 acc[4][2] = {};
    int t = threadIdx.x;
    int tm = t >> 4, tn = t & 15;
    int kk0 = t >> 4, n4 = (t & 15)*4;
    for (int k0 = 0; k0 < 512; k0 += 16) {
        *(float4*)(As + kk0*64 + n4) = *(const float4*)(A + (size_t)(k0+kk0)*NSLOT + n4);
        *(float4*)(Bs + kk0*64 + n4) = *(const float4*)(B + (size_t)(k0+kk0)*DIM + n4);
        __syncthreads();
        #pragma unroll
        for (int kk = 0; kk < 16; kk++) {
            ulonglong2 a2 = *(ulonglong2*)(As + kk*64 + tm*4);   // slot pairs
            float4 bb = *(float4*)(Bs + kk*64 + tn*4);           // dims
            u64 q0 = PK1(bb.x), q1 = PK1(bb.y), q2 = PK1(bb.z), q3 = PK1(bb.w);
            FMA2(acc[0][0], a2.x, q0); FMA2(acc[0][1], a2.y, q0);
            FMA2(acc[1][0], a2.x, q1); FMA2(acc[1][1], a2.y, q1);
            FMA2(acc[2][0], a2.x, q2); FMA2(acc[2][1], a2.y, q2);
            FMA2(acc[3][0], a2.x, q3); FMA2(acc[3][1], a2.y, q3);
        }
        __syncthreads();
    }
    #pragma unroll
    for (int p = 0; p < 2; p++) {
        float2 f0 = UPK(acc[0][p]), f1 = UPK(acc[1][p]), f2 = UPK(acc[2][p]), f3 = UPK(acc[3][p]);
        int slot = tm*4 + p*2;
        float4 r0 = {f0.x, f1.x, f2.x, f3.x};
        float4 r1 = {f0.y, f1.y, f2.y, f3.y};
        *(float4*)(g_accpart + ((size_t)((ps*BATCH + b)*NSLOT) + slot  )*DIM + dt*64 + tn*4) = r0;
        *(float4*)(g_accpart + ((size_t)((ps*BATCH + b)*NSLOT) + slot+1)*DIM + dt*64 + tn*4) = r1;
    }
}

// ---------------- fused colsum + template update + LN_m. grid 8 ----------------
#define FIN_SMEM_FLOATS (16384 + 256 + 64)
__global__ __launch_bounds__(256) void finalize_kernel(const float* __restrict__ g,
                                                       const float* __restrict__ bb) {
    extern __shared__ float sm[];
    float* tv   = sm;          // 64 x 256 new template values
    float* csp  = sm + 16384;  // 4 x 64
    float* csin = sm + 16640;  // 64
    int b = blockIdx.x, t = threadIdx.x;

    // colsum
    {
        int part4 = t >> 6, n = t & 63;
        float s = 0.f;
        #pragma unroll
        for (int lb = 0; lb < 16; lb++)
            s += g_colsum_part[((size_t)b*64 + part4*16 + lb)*NSLOT + n];
        csp[part4*64 + n] = s;
    }
    __syncthreads();
    if (t < 64) {
        float tot = csp[t] + csp[64+t] + csp[128+t] + csp[192+t];
        g_colsum[b*NSLOT + t] = tot;
        csin[t] = 1.0f / tot;
    }
    __syncthreads();

    // accumulate split-K partials + residual
    for (int n = 0; n < NSLOT; n++) {
        float s = 0.f;
        #pragma unroll
        for (int p = 0; p < 8; p++)
            s += g_accpart[((size_t)((p*BATCH + b)*NSLOT) + n)*DIM + t];
        size_t idx = ((size_t)(b*NSLOT) + n)*DIM + t;
        float val = g_templates[idx] + s * csin[n];
        g_templates[idx] = val;
        tv[n*256 + t] = val;
    }
    __syncthreads();

    // LN_m from smem -> g_tbuf
    {
        int r = t >> 2, part = t & 3;
        const float* row = tv + r*256 + part*64;
        float s = 0.f, sq = 0.f;
        #pragma unroll
        for (int i = 0; i < 64; i += 4) {
            float4 v = *(const float4*)(row + i);
            s += v.x+v.y+v.z+v.w;
            sq += v.x*v.x + v.y*v.y + v.z*v.z + v.w*v.w;
        }
        s  += __shfl_xor_sync(0xffffffffu, s, 1);  s  += __shfl_xor_sync(0xffffffffu, s, 2);
        sq += __shfl_xor_sync(0xffffffffu, sq, 1); sq += __shfl_xor_sync(0xffffffffu, sq, 2);
        float mu = s * (1.0f/256.0f);
        float rs = rsqrtf(sq * (1.0f/256.0f) - mu*mu + 1e-5f);
        float* drow = g_tbuf + ((size_t)(b*NSLOT) + r)*DIM + part*64;
        #pragma unroll
        for (int i = 0; i < 64; i += 4) {
            float4 v = *(const float4*)(row + i);
            float4 gg = *(const float4*)(g + part*64 + i);
            float4 bv = *(const float4*)(bb + part*64 + i);
            float4 o;
            o.x = (v.x - mu)*rs*gg.x + bv.x;
            o.y = (v.y - mu)*rs*gg.y + bv.y;
            o.z = (v.z - mu)*rs*gg.z + bv.z;
            o.w = (v.w - mu)*rs*gg.w + bv.w;
            *(float4*)(drow + i) = o;
        }
    }
}

// ---------------- outputs ----------------
__global__ void out_templates_kernel(float* __restrict__ out) {
    int b = blockIdx.x, d = threadIdx.x;
    for (int n = 0; n < NSLOT; n++)
        out[((size_t)(b*DIM) + d)*NSLOT + n] = g_templates[((size_t)(b*NSLOT) + n)*DIM + d];
}

__global__ void out_attn_kernel(float* __restrict__ out) {
    int n = blockIdx.x, b = blockIdx.y, t = threadIdx.x;
    float inv = 1.0f / g_colsum[b*NSLOT + n];
    size_t base = (size_t)BATCH*DIM*NSLOT + ((size_t)(b*NSLOT + n))*LTOK;
    for (int k = 0; k < 16; k++) {
        int l = k*256 + t;
        out[base + l] = g_attn[((size_t)b*LTOK + l)*NSLOT + n] * inv;
    }
}

// ---------------- launch ----------------
extern "C" void kernel_launch(void* const* d_in, const int* in_sizes, int n_in,
                              void* d_out, int out_size) {
    const float* x       = (const float*)d_in[0];
    const float* tinit   = (const float*)d_in[1];
    const float* conv_w  = (const float*)d_in[2];
    const float* conv_b  = (const float*)d_in[3];
    const float* Wq      = (const float*)d_in[4];
    const float* Wk      = (const float*)d_in[5];
    const float* Wv      = (const float*)d_in[6];
    const float* ln_in_g = (const float*)d_in[7];
    const float* ln_in_b = (const float*)d_in[8];
    const float* ln_t_g  = (const float*)d_in[9];
    const float* ln_t_b  = (const float*)d_in[10];
    const float* ln_m_g  = (const float*)d_in[11];
    const float* ln_m_b  = (const float*)d_in[12];
    const float* W1      = (const float*)d_in[13];
    const float* b1      = (const float*)d_in[14];
    const float* W2      = (const float*)d_in[15];
    const float* b2      = (const float*)d_in[16];
    float* out = (float*)d_out;

    cudaFuncSetAttribute(conv_ln_kv_kernel, cudaFuncAttributeMaxDynamicSharedMemorySize,
                         CONV_SMEM_FLOATS * 4);
    cudaFuncSetAttribute(gemm_q_kernel, cudaFuncAttributeMaxDynamicSharedMemorySize, (16384+1024)*4);
    cudaFuncSetAttribute(gemm_h_kernel, cudaFuncAttributeMaxDynamicSharedMemorySize, (16384+1024)*4);
    cudaFuncSetAttribute(gemm_o_kernel, cudaFuncAttributeMaxDynamicSharedMemorySize, GEMMO_SMEM_FLOATS*4);
    cudaFuncSetAttribute(finalize_kernel, cudaFuncAttributeMaxDynamicSharedMemorySize, FIN_SMEM_FLOATS*4);

    wt_transpose_kernel<<<3456, 256>>>(conv_w);
    templates_init_kernel<<<8, 256>>>(tinit);
    conv_ln_kv_kernel<<<2048, 256, CONV_SMEM_FLOATS * 4>>>(x, conv_b, ln_in_g, ln_in_b, Wk, Wv);

    for (int it = 0; it < 6; it++) {
        gemm_q_kernel<<<dim3(4, 8), 256, (16384+1024)*4>>>(Wq, ln_t_g, ln_t_b);
        attn_softmax_kernel<<<dim3(64, 8), 256>>>();
        gemm_c_kernel<<<dim3(4, 8, 8), 256>>>();
        finalize_kernel<<<8, 256, FIN_SMEM_FLOATS*4>>>(ln_m_g, ln_m_b);
        gemm_h_kernel<<<dim3(8, 8), 256, (16384+1024)*4>>>(W1, b1);
        gemm_o_kernel<<<dim3(4, 8), 256, GEMMO_SMEM_FLOATS*4>>>(W2, b2);
    }

    out_templates_kernel<<<8, 256>>>(out);
    out_attn_kernel<<<dim3(64, 8), 256>>>(out);
}